// round 1
// baseline (speedup 1.0000x reference)
#include <cuda_runtime.h>

#define Nn      1000
#define INF_    32
#define Hh      128
#define Mm      128
#define DEGc    16
#define Pp      2
#define OUTn    10
#define NSTART  64
#define MAXM    10000
#define CAPQ    (NSTART + MAXM*DEGc)
#define THRv    (1.0f - 1e-7f)

typedef unsigned long long ull;

__device__ float g_feats[Nn*Hh];
__device__ float g_msgs[MAXM*Mm];
__device__ int   g_qn[CAPQ];

__device__ __forceinline__ ull pack2(float a, float b){
    ull r; asm("mov.b64 %0, {%1,%2};" : "=l"(r) : "f"(a), "f"(b)); return r;
}
__device__ __forceinline__ ull fma2(ull a, ull b, ull c){
    ull d; asm("fma.rn.f32x2 %0, %1, %2, %3;" : "=l"(d) : "l"(a), "l"(b), "l"(c)); return d;
}

// ---------------- encoder: feats0 = xa @ enc_w + enc_b ----------------
__global__ void enc_kernel(const float* __restrict__ xa,
                           const float* __restrict__ ew,
                           const float* __restrict__ eb)
{
    __shared__ float sx[INF_];
    int nrow = blockIdx.x;
    if (threadIdx.x < INF_) sx[threadIdx.x] = xa[nrow*INF_ + threadIdx.x];
    __syncthreads();
    int h = threadIdx.x;
    float a = eb[h];
    #pragma unroll
    for (int i = 0; i < INF_; i++) a = fmaf(sx[i], ew[i*Hh + h], a);
    g_feats[nrow*Hh + h] = a;
}

// ---------------- shared memory layout (floats) ----------------
#define OFF_NSW  0
#define OFF_RED  (OFF_NSW + 256*Hh)      // 32768
#define OFF_X    (OFF_RED + 8*Hh)        // +1024
#define OFF_AW   (OFF_X + 256)
#define OFF_NSB  (OFF_AW + 256)
#define OFF_NMB  (OFF_NSB + 128)
#define OFF_G    (OFF_NMB + 128)
#define OFF_TACT (OFF_G + 128)
#define OFF_NB   (OFF_TACT + Nn)         // ints (16)
#define OFF_CI   (OFF_NB + 16)           // ints (8): head,tail,steps,pc,node,eidx,done
#define OFF_CF   (OFF_CI + 8)            // floats (4): act_b, new_act
#define SMEM_FLOATS (OFF_CF + 4)
#define SMEM_BYTES  (SMEM_FLOATS * 4)

// ---------------- serial queue kernel (1 block, 512 threads) ----------------
__global__ void __launch_bounds__(512, 1) serial_kernel(
    const float* __restrict__ fm,  const int*   __restrict__ nbr,
    const float* __restrict__ nsw, const float* __restrict__ nsb,
    const float* __restrict__ nmw, const float* __restrict__ nmb,
    const float* __restrict__ aw,  const float* __restrict__ ab,
    const float* __restrict__ dw,  const float* __restrict__ db,
    float* __restrict__ out)
{
    extern __shared__ float sm[];
    float* s_nsw  = sm + OFF_NSW;
    float* s_red  = sm + OFF_RED;
    float* s_x    = sm + OFF_X;
    float* s_aw   = sm + OFF_AW;
    float* s_nsb  = sm + OFF_NSB;
    float* s_nmb  = sm + OFF_NMB;
    float* s_g    = sm + OFF_G;
    float* s_tact = sm + OFF_TACT;
    int*   s_nb   = (int*)(sm + OFF_NB);
    int*   s_ci   = (int*)(sm + OFF_CI);
    float* s_cf   = sm + OFF_CF;

    const int t = threadIdx.x;
    const int w = t >> 5, l = t & 31;
    const int j2 = ((w & 1) << 5) | l;   // output pair index 0..63 -> outputs (2*j2, 2*j2+1)
    const int r  = w >> 1;               // k-group 0..7 -> k in [32r, 32r+32)

    // ---- init ----
    for (int i = t; i < (256*Hh)/4; i += 512)
        ((float4*)s_nsw)[i] = ((const float4*)nsw)[i];
    if (t < 256) s_aw[t] = aw[t];
    if (t < 128) { s_nsb[t] = nsb[t]; s_nmb[t] = nmb[t]; s_g[t] = 0.f; }
    for (int i = t; i < Nn; i += 512) s_tact[i] = 0.f;
    if (t == 0) {
        s_ci[0] = 0; s_ci[1] = NSTART; s_ci[2] = 0; s_ci[3] = 0; s_ci[6] = 0;
        s_cf[0] = ab[0];
    }

    // nm_w held entirely in registers, packed as f32x2 pairs
    ull wnm[32];
    #pragma unroll
    for (int i = 0; i < 32; i++) {
        const float2 v = *(const float2*)(nmw + (32*r + i)*Hh + 2*j2);
        wnm[i] = pack2(v.x, v.y);
    }
    __syncthreads();

    for (;;) {
        // ---- phase S: warp 0 scans queue for next productive step ----
        if (w == 0) {
            int head = s_ci[0], tail = s_ci[1], steps = s_ci[2];
            int lim = tail;
            { int be = head + (MAXM - steps); if (be < lim) lim = be; }
            int hh = head;
            bool found = false;
            while (hh < lim) {
                int idx = hh + l;
                int nodel = 0; float ta = 2.0f;
                bool v = idx < lim;
                if (v) { nodel = (idx < NSTART) ? idx : g_qn[idx]; ta = s_tact[nodel]; }
                unsigned bal = __ballot_sync(0xffffffffu, v && (ta <= THRv));
                if (bal) {
                    int first = __ffs(bal) - 1;
                    if (l == first) { s_ci[4] = nodel; s_ci[5] = idx; }
                    if (l == 0) {
                        s_ci[2] = steps + (hh - head) + first + 1;
                        s_ci[0] = hh + first + 1;
                    }
                    found = true; break;
                }
                hh += 32;
            }
            if (!found && l == 0) s_ci[6] = 1;   // budget exhausted or queue drained
        }
        __syncthreads();
        if (s_ci[6]) break;
        const int node = s_ci[4], e = s_ci[5];
        const int pc = s_ci[3], tailv = s_ci[1];

        // ---- phase L: gather x = [feats[node], msg] into smem ----
        if (t < 64) {
            float4 v;
            if (t < 32) v = ((const float4*)(g_feats + node*Hh))[t];
            else {
                const float* mp = (e < NSTART) ? (fm + e*Mm)
                                               : (g_msgs + ((e - NSTART) >> 4)*Mm);
                v = ((const float4*)mp)[t - 32];
            }
            ((float4*)s_x)[t] = v;
        } else if (t < 64 + DEGc) {
            s_nb[t - 64] = nbr[node*DEGc + (t - 64)];
        }
        __syncthreads();

        // ---- phase A/NS: act gate (warp 15) + ns partials (all warps) ----
        if (w == 15) {
            float a = 0.f;
            #pragma unroll
            for (int i = 0; i < 8; i++) a = fmaf(s_x[l + 32*i], s_aw[l + 32*i], a);
            #pragma unroll
            for (int o = 16; o; o >>= 1) a += __shfl_xor_sync(0xffffffffu, a, o);
            if (l == 0) {
                float z = a + s_cf[0];
                float cand = 1.f / (1.f + expf(-z));
                float ta = s_tact[node];
                float na = (ta + cand > 1.0f) ? (1.0f - ta) : cand;
                s_cf[1] = na;
                s_tact[node] = ta + na;
            }
        }
        {
            ull acc = 0ull;
            const ull* wb = ((const ull*)s_nsw) + j2;
            #pragma unroll
            for (int ii = 0; ii < 8; ii++) {
                float4 xv = ((const float4*)s_x)[8*r + ii];   // warp-uniform address
                int k0 = (32*r + 4*ii) * 64;
                acc = fma2(pack2(xv.x, xv.x), wb[k0],       acc);
                acc = fma2(pack2(xv.y, xv.y), wb[k0 +  64], acc);
                acc = fma2(pack2(xv.z, xv.z), wb[k0 + 128], acc);
                acc = fma2(pack2(xv.w, xv.w), wb[k0 + 192], acc);
            }
            ((ull*)s_red)[r*64 + j2] = acc;
        }
        __syncthreads();

        // ---- ns reduce -> relu -> overwrite first half of x with ns ----
        if (t < 128) {
            float v = s_nsb[t];
            #pragma unroll
            for (int rr = 0; rr < 8; rr++) v += s_red[rr*128 + t];
            s_x[t] = fmaxf(v, 0.f);
        }
        __syncthreads();

        // ---- phase NM: [ns, msg] @ nm_w, weights in registers ----
        {
            ull acc = 0ull;
            #pragma unroll
            for (int ii = 0; ii < 8; ii++) {
                float4 xv = ((const float4*)s_x)[8*r + ii];
                acc = fma2(pack2(xv.x, xv.x), wnm[4*ii    ], acc);
                acc = fma2(pack2(xv.y, xv.y), wnm[4*ii + 1], acc);
                acc = fma2(pack2(xv.z, xv.z), wnm[4*ii + 2], acc);
                acc = fma2(pack2(xv.w, xv.w), wnm[4*ii + 3], acc);
            }
            ((ull*)s_red)[r*64 + j2] = acc;
        }
        __syncthreads();

        // ---- commit: message, feats, graph readout, enqueue ----
        if (t < 128) {
            float v = s_nmb[t];
            #pragma unroll
            for (int rr = 0; rr < 8; rr++) v += s_red[rr*128 + t];
            g_msgs[pc*Mm + t] = v;
            float nsv = s_x[t];
            g_feats[node*Hh + t] = nsv;
            s_g[t] += nsv * s_cf[1];
        } else if (t < 128 + DEGc) {
            g_qn[tailv + (t - 128)] = s_nb[t - 128];
        } else if (t == 160) {
            s_ci[3] = pc + 1; s_ci[1] = tailv + DEGc;
        }
        __syncthreads();
    }

    // ---- decode: logits = g @ dec_w + dec_b, then log_softmax ----
    if (t < Pp*OUTn) {
        int p = t / OUTn, o = t % OUTn;
        float z = db[p*OUTn + o];
        #pragma unroll 8
        for (int h = 0; h < Hh; h++) z = fmaf(s_g[h], dw[(p*Hh + h)*OUTn + o], z);
        s_red[t] = z;
    }
    __syncthreads();
    if (t < Pp) {
        float mx = -1e30f;
        for (int o = 0; o < OUTn; o++) mx = fmaxf(mx, s_red[t*OUTn + o]);
        float se = 0.f;
        for (int o = 0; o < OUTn; o++) se += expf(s_red[t*OUTn + o] - mx);
        float ls = logf(se);
        for (int o = 0; o < OUTn; o++) out[t*OUTn + o] = s_red[t*OUTn + o] - mx - ls;
    }
}

extern "C" void kernel_launch(void* const* d_in, const int* in_sizes, int n_in,
                              void* d_out, int out_size)
{
    const float* xa  = (const float*)d_in[0];
    const float* fm  = (const float*)d_in[1];
    const int*   nbv = (const int*)  d_in[2];
    // d_in[3] = num_starts (compile-time 64 for this problem)
    const float* ew  = (const float*)d_in[4];
    const float* eb  = (const float*)d_in[5];
    const float* nsw = (const float*)d_in[6];
    const float* nsb = (const float*)d_in[7];
    const float* nmw = (const float*)d_in[8];
    const float* nmb = (const float*)d_in[9];
    const float* aw  = (const float*)d_in[10];
    const float* ab  = (const float*)d_in[11];
    const float* dw  = (const float*)d_in[12];
    const float* db  = (const float*)d_in[13];
    float* out = (float*)d_out;

    cudaFuncSetAttribute(serial_kernel,
                         cudaFuncAttributeMaxDynamicSharedMemorySize, SMEM_BYTES);

    enc_kernel<<<Nn, Hh>>>(xa, ew, eb);
    serial_kernel<<<1, 512, SMEM_BYTES>>>(fm, nbv, nsw, nsb, nmw, nmb,
                                          aw, ab, dw, db, out);
}